// round 1
// baseline (speedup 1.0000x reference)
#include <cuda_runtime.h>
#include <cuda_bf16.h>
#include <mma.h>

using namespace nvcuda;

#define N_TOK 1024
#define DIM   2048
#define FDIM  5632
#define NEXP  8
#define RANK  16
#define LSCALE 2.0f

// ---------------- scratch (device globals; no allocations allowed) ----------------
__device__ float g_l1[N_TOK * 128];                 // x @ A1^T  [N, E*R]
__device__ float g_l3[N_TOK * 128];                 // x @ A3^T
__device__ float g_Y1[N_TOK * FDIM];                // x @ W1^T
__device__ float g_Y3[N_TOK * FDIM];                // x @ W3^T
__device__ float g_sbuf[2 * N_TOK * FDIM];          // s per (token, slot k)
__device__ float g_smix[N_TOK * FDIM];              // w0*s0 + w1*s1
__device__ float g_l2acc[2 * N_TOK * RANK];         // sum_f s * A2
__device__ float g_topw[2 * N_TOK];
__device__ int   g_topi[2 * N_TOK];
__device__ int   g_cnt[NEXP];
__device__ int   g_list[NEXP * N_TOK];              // codes (n<<1)|k grouped by expert

// ---------------- utility ----------------
__device__ __forceinline__ void cp16(float* smem_dst, const float* gsrc) {
    unsigned s = (unsigned)__cvta_generic_to_shared(smem_dst);
    asm volatile("cp.async.cg.shared.global [%0], [%1], 16;\n" :: "r"(s), "l"(gsrc));
}

// ---------------- zero scratch that is accumulated into ----------------
__global__ void zero_kernel() {
    int i = blockIdx.x * blockDim.x + threadIdx.x;
    if (i < 2 * N_TOK * RANK) g_l2acc[i] = 0.f;
    if (i < NEXP) g_cnt[i] = 0;
}

// ---------------- router: logits, top-2, renormalized weights ----------------
__global__ __launch_bounds__(256) void router_kernel(const float* __restrict__ x,
                                                     const float* __restrict__ gate,
                                                     float* __restrict__ logits_out) {
    int n = blockIdx.x;
    __shared__ float xs[DIM];
    __shared__ float lg[NEXP];
    for (int i = threadIdx.x; i < DIM; i += 256) xs[i] = x[(size_t)n * DIM + i];
    __syncthreads();
    int wid = threadIdx.x >> 5, lane = threadIdx.x & 31;
    const float* g = gate + (size_t)wid * DIM;   // warp wid handles expert wid
    float s = 0.f;
    for (int d = lane; d < DIM; d += 32) s += xs[d] * g[d];
    #pragma unroll
    for (int o = 16; o; o >>= 1) s += __shfl_xor_sync(0xffffffffu, s, o);
    if (lane == 0) lg[wid] = s;
    __syncthreads();
    if (threadIdx.x == 0) {
        #pragma unroll
        for (int e = 0; e < NEXP; e++) logits_out[n * NEXP + e] = lg[e];
        int i0 = 0; float v0 = lg[0];
        #pragma unroll
        for (int e = 1; e < NEXP; e++) if (lg[e] > v0) { v0 = lg[e]; i0 = e; }
        int i1 = -1; float v1 = -1e30f;
        #pragma unroll
        for (int e = 0; e < NEXP; e++) if (e != i0 && lg[e] > v1) { v1 = lg[e]; i1 = e; }
        float w0 = 1.f / (1.f + expf(v1 - v0));   // = p0/(p0+p1), renormalized
        g_topi[2 * n] = i0; g_topi[2 * n + 1] = i1;
        g_topw[2 * n] = w0; g_topw[2 * n + 1] = 1.f - w0;
    }
}

// ---------------- group (token, slot) pairs by expert ----------------
__global__ void build_lists_kernel() {
    int n = blockIdx.x * blockDim.x + threadIdx.x;
    if (n >= N_TOK) return;
    #pragma unroll
    for (int k = 0; k < 2; k++) {
        int e = g_topi[2 * n + k];
        int p = atomicAdd(&g_cnt[e], 1);
        g_list[e * N_TOK + p] = (n << 1) | k;
    }
}

// ---------------- tf32 wmma GEMM: C[M,Ncols] = A[M,K] * B[Ncols,K]^T ----------------
#define GBM 128
#define GBN 128
#define GBK 32
#define GLD (GBK + 4)   // 36 floats/row -> 144B, 16B-aligned rows

__global__ __launch_bounds__(256) void gemm_tn_kernel(const float* __restrict__ A,
                                                      const float* __restrict__ B,
                                                      float* __restrict__ C,
                                                      int M, int Ncols, int K) {
    extern __shared__ __align__(16) float sm[];
    float* As = sm;                       // [2][GBM*GLD]
    float* Bs = sm + 2 * GBM * GLD;       // [2][GBN*GLD]
    int bm = blockIdx.y, bn = blockIdx.x;
    const float* Ag = A + (size_t)bm * GBM * K;
    const float* Bg = B + (size_t)bn * GBN * K;
    int tid = threadIdx.x;
    int lrow = tid >> 3;
    int lcol = (tid & 7) * 4;
    int nk = K / GBK;

    // prologue: stage tile 0
    {
        #pragma unroll
        for (int i = 0; i < 4; i++) {
            int r = lrow + i * 32;
            cp16(&As[r * GLD + lcol], Ag + (size_t)r * K + lcol);
            cp16(&Bs[r * GLD + lcol], Bg + (size_t)r * K + lcol);
        }
        asm volatile("cp.async.commit_group;\n");
    }

    int wid = tid >> 5;
    int wm = wid >> 2, wn = wid & 3;      // 2x4 warp grid; warp tile 64x32
    wmma::fragment<wmma::accumulator, 16, 16, 8, float> acc[4][2];
    #pragma unroll
    for (int i = 0; i < 4; i++)
        #pragma unroll
        for (int j = 0; j < 2; j++) wmma::fill_fragment(acc[i][j], 0.f);

    for (int kt = 0; kt < nk; kt++) {
        int buf = kt & 1;
        if (kt + 1 < nk) {
            int nb = (kt + 1) & 1;
            const float* a = Ag + (size_t)(kt + 1) * GBK;
            const float* b = Bg + (size_t)(kt + 1) * GBK;
            #pragma unroll
            for (int i = 0; i < 4; i++) {
                int r = lrow + i * 32;
                cp16(&As[nb * GBM * GLD + r * GLD + lcol], a + (size_t)r * K + lcol);
                cp16(&Bs[nb * GBN * GLD + r * GLD + lcol], b + (size_t)r * K + lcol);
            }
            asm volatile("cp.async.commit_group;\n");
            asm volatile("cp.async.wait_group 1;\n");
        } else {
            asm volatile("cp.async.wait_group 0;\n");
        }
        __syncthreads();
        const float* Ab = As + buf * GBM * GLD;
        const float* Bb = Bs + buf * GBN * GLD;
        #pragma unroll
        for (int kk = 0; kk < GBK; kk += 8) {
            wmma::fragment<wmma::matrix_a, 16, 16, 8, wmma::precision::tf32, wmma::row_major> af[4];
            wmma::fragment<wmma::matrix_b, 16, 16, 8, wmma::precision::tf32, wmma::col_major> bf[2];
            #pragma unroll
            for (int i = 0; i < 4; i++) {
                wmma::load_matrix_sync(af[i], Ab + (wm * 64 + i * 16) * GLD + kk, GLD);
                #pragma unroll
                for (int t = 0; t < af[i].num_elements; t++)
                    af[i].x[t] = wmma::__float_to_tf32(af[i].x[t]);
            }
            #pragma unroll
            for (int j = 0; j < 2; j++) {
                wmma::load_matrix_sync(bf[j], Bb + (wn * 32 + j * 16) * GLD + kk, GLD);
                #pragma unroll
                for (int t = 0; t < bf[j].num_elements; t++)
                    bf[j].x[t] = wmma::__float_to_tf32(bf[j].x[t]);
            }
            #pragma unroll
            for (int i = 0; i < 4; i++)
                #pragma unroll
                for (int j = 0; j < 2; j++)
                    wmma::mma_sync(acc[i][j], af[i], bf[j], acc[i][j]);
        }
        __syncthreads();
    }
    #pragma unroll
    for (int i = 0; i < 4; i++)
        #pragma unroll
        for (int j = 0; j < 2; j++)
            wmma::store_matrix_sync(
                C + (size_t)(bm * GBM + wm * 64 + i * 16) * Ncols + bn * GBN + wn * 32 + j * 16,
                acc[i][j], Ncols, wmma::mem_row_major);
}

// ---------------- fused LoRA-B + SwiGLU per active (token, expert) ----------------
__global__ __launch_bounds__(128) void expert_kernel(const float* __restrict__ B1,
                                                     const float* __restrict__ B3) {
    int e = blockIdx.y;
    int f0 = blockIdx.x * 128;
    int f = threadIdx.x;
    __shared__ float B1s[16][128];
    __shared__ float B3s[16][128];
    __shared__ float lv[8][32];
    __shared__ int scode[8];

    {
        const float4* p1 = (const float4*)(B1 + (size_t)(e * FDIM + f0 + f) * RANK);
        const float4* p3 = (const float4*)(B3 + (size_t)(e * FDIM + f0 + f) * RANK);
        #pragma unroll
        for (int q = 0; q < 4; q++) {
            float4 v = p1[q];
            B1s[q * 4 + 0][f] = v.x; B1s[q * 4 + 1][f] = v.y;
            B1s[q * 4 + 2][f] = v.z; B1s[q * 4 + 3][f] = v.w;
            float4 u = p3[q];
            B3s[q * 4 + 0][f] = u.x; B3s[q * 4 + 1][f] = u.y;
            B3s[q * 4 + 2][f] = u.z; B3s[q * 4 + 3][f] = u.w;
        }
    }
    int cnt = g_cnt[e];
    for (int t0 = 0; t0 < cnt; t0 += 8) {
        int nt = (cnt - t0 < 8) ? (cnt - t0) : 8;
        __syncthreads();   // protects B-tiles (first iter) and lv reuse
        for (int idx = threadIdx.x; idx < nt * 32; idx += 128) {
            int ti = idx >> 5, r = idx & 31;
            int code = g_list[e * N_TOK + t0 + ti];
            int n = code >> 1;
            lv[ti][r] = (r < 16) ? g_l1[n * 128 + e * 16 + r]
                                 : g_l3[n * 128 + e * 16 + (r - 16)];
            if (r == 0) scode[ti] = code;
        }
        __syncthreads();
        for (int ti = 0; ti < nt; ti++) {
            int code = scode[ti];
            int n = code >> 1, k = code & 1;
            float b1 = g_Y1[(size_t)n * FDIM + f0 + f];
            float b3 = g_Y3[(size_t)n * FDIM + f0 + f];
            float h1 = 0.f, h3 = 0.f;
            #pragma unroll
            for (int r = 0; r < 16; r++) {
                h1 += lv[ti][r]      * B1s[r][f];
                h3 += lv[ti][16 + r] * B3s[r][f];
            }
            h1 = b1 + LSCALE * h1;
            h3 = b3 + LSCALE * h3;
            float sg = 1.f / (1.f + __expf(-h1));
            g_sbuf[(size_t)(2 * n + k) * FDIM + f0 + f] = h1 * sg * h3;
        }
    }
}

// ---------------- s_mix = w0*s0 + w1*s1 ----------------
__global__ void mix_kernel() {
    int idx = blockIdx.x * blockDim.x + threadIdx.x;
    if (idx >= N_TOK * FDIM) return;
    int n = idx / FDIM;
    int f = idx - n * FDIM;
    float w0 = g_topw[2 * n], w1 = g_topw[2 * n + 1];
    g_smix[idx] = w0 * g_sbuf[(size_t)(2 * n) * FDIM + f]
                + w1 * g_sbuf[(size_t)(2 * n + 1) * FDIM + f];
}

// ---------------- l2acc[n,k,r] = sum_f s * A2[e,r,f] (expert-grouped) ----------------
__global__ __launch_bounds__(128) void l2_kernel(const float* __restrict__ A2) {
    int e = blockIdx.y;
    int f0 = blockIdx.x * 512;
    __shared__ float A2s[16][516];   // padded: conflict-free across rr
    __shared__ float ss[512];
    for (int r = 0; r < 16; r++)
        for (int c = threadIdx.x; c < 512; c += 128)
            A2s[r][c] = A2[(size_t)(e * 16 + r) * FDIM + f0 + c];
    int rr = threadIdx.x >> 3, jj = threadIdx.x & 7;
    int cnt = g_cnt[e];
    for (int ti = 0; ti < cnt; ti++) {
        int code = g_list[e * N_TOK + ti];   // code == 2n+k
        __syncthreads();
        for (int c = threadIdx.x; c < 512; c += 128)
            ss[c] = g_sbuf[(size_t)code * FDIM + f0 + c];
        __syncthreads();
        float acc = 0.f;
        #pragma unroll 8
        for (int t = 0; t < 64; t++) {
            int c = t * 8 + jj;
            acc += ss[c] * A2s[rr][c];
        }
        acc += __shfl_xor_sync(0xffffffffu, acc, 1);
        acc += __shfl_xor_sync(0xffffffffu, acc, 2);
        acc += __shfl_xor_sync(0xffffffffu, acc, 4);
        if (jj == 0) atomicAdd(&g_l2acc[code * 16 + rr], acc);
    }
}

// ---------------- out += sum_k 2*w_k * (l2acc[n,k,:] . B2[e_k,d,:]) ----------------
__global__ __launch_bounds__(256) void final_kernel(const float* __restrict__ B2,
                                                    float* __restrict__ out) {
    int n = blockIdx.y;
    int d = blockIdx.x * 256 + threadIdx.x;
    __shared__ float lw[32];
    __shared__ int se[2];
    if (threadIdx.x < 32) {
        int k = threadIdx.x >> 4;
        lw[threadIdx.x] = g_l2acc[n * 32 + threadIdx.x] * (LSCALE * g_topw[2 * n + k]);
        if (threadIdx.x < 2) se[threadIdx.x] = g_topi[2 * n + threadIdx.x];
    }
    __syncthreads();
    float o = out[(size_t)n * DIM + d];
    #pragma unroll
    for (int k = 0; k < 2; k++) {
        const float4* b2 = (const float4*)(B2 + (size_t)(se[k] * DIM + d) * RANK);
        float a = 0.f;
        #pragma unroll
        for (int q = 0; q < 4; q++) {
            float4 v = b2[q];
            a += lw[k * 16 + q * 4 + 0] * v.x + lw[k * 16 + q * 4 + 1] * v.y
               + lw[k * 16 + q * 4 + 2] * v.z + lw[k * 16 + q * 4 + 3] * v.w;
        }
        o += a;
    }
    out[(size_t)n * DIM + d] = o;
}

// ---------------- host ----------------
extern "C" void kernel_launch(void* const* d_in, const int* in_sizes, int n_in,
                              void* d_out, int out_size) {
    const float* x    = (const float*)d_in[0];
    const float* gate = (const float*)d_in[1];
    const float* W1   = (const float*)d_in[2];
    const float* W3   = (const float*)d_in[3];
    const float* W2   = (const float*)d_in[4];
    const float* A1   = (const float*)d_in[5];
    const float* B1   = (const float*)d_in[6];
    const float* A3   = (const float*)d_in[7];
    const float* B3   = (const float*)d_in[8];
    const float* A2   = (const float*)d_in[9];
    const float* B2   = (const float*)d_in[10];
    float* out = (float*)d_out;
    float* logits = out + (size_t)N_TOK * DIM;   // output order: (out, logits)

    float *p_l1, *p_l3, *p_Y1, *p_Y3, *p_smix;
    cudaGetSymbolAddress((void**)&p_l1,   g_l1);
    cudaGetSymbolAddress((void**)&p_l3,   g_l3);
    cudaGetSymbolAddress((void**)&p_Y1,   g_Y1);
    cudaGetSymbolAddress((void**)&p_Y3,   g_Y3);
    cudaGetSymbolAddress((void**)&p_smix, g_smix);

    const int smem = (2 * GBM * GLD + 2 * GBN * GLD) * 4;   // 73728 B
    cudaFuncSetAttribute(gemm_tn_kernel, cudaFuncAttributeMaxDynamicSharedMemorySize, smem);

    zero_kernel<<<128, 256>>>();
    router_kernel<<<N_TOK, 256>>>(x, gate, logits);
    build_lists_kernel<<<4, 256>>>();

    // LoRA-A projections: [N,128] = x @ A{1,3}^T   (A is [E*R, D] row-major)
    gemm_tn_kernel<<<dim3(1, N_TOK / GBM), 256, smem>>>(x, A1, p_l1, N_TOK, 128, DIM);
    gemm_tn_kernel<<<dim3(1, N_TOK / GBM), 256, smem>>>(x, A3, p_l3, N_TOK, 128, DIM);
    // Base up-projections
    gemm_tn_kernel<<<dim3(FDIM / GBN, N_TOK / GBM), 256, smem>>>(x, W1, p_Y1, N_TOK, FDIM, DIM);
    gemm_tn_kernel<<<dim3(FDIM / GBN, N_TOK / GBM), 256, smem>>>(x, W3, p_Y3, N_TOK, FDIM, DIM);

    expert_kernel<<<dim3(FDIM / 128, NEXP), 128>>>(B1, B3);
    mix_kernel<<<(N_TOK * FDIM + 255) / 256, 256>>>();
    l2_kernel<<<dim3(FDIM / 512, NEXP), 128>>>(A2);

    // Down projection straight into d_out
    gemm_tn_kernel<<<dim3(DIM / GBN, N_TOK / GBM), 256, smem>>>(p_smix, W2, out, N_TOK, DIM, FDIM);
    final_kernel<<<dim3(DIM / 256, N_TOK), 256>>>(B2, out);
}